// round 13
// baseline (speedup 1.0000x reference)
#include <cuda_runtime.h>
#include <cuda_fp16.h>
#include <cstdint>
#include <mma.h>
using namespace nvcuda;

#define NN   50000
#define EE   800000
#define EDEC 100000
#define F1   128     // H1*HID
#define F2   256     // H2*HID
#define SPLIT 25088  // layer-1/2 pipeline split (128-aligned)

// ---------------- scratch (device globals: no allocation allowed) -------------
// Counter protocol: g_cnt and g_total are zero at kernel_launch entry (static
// init on first call; layer-2 agg_kernel re-zeroes them before exiting), so
// the histogram can run immediately at stream-fork time.
__device__ __half g_x16[NN * F1];   // x in fp16 (gemm1 A)
__device__ __half g_w1h[F1 * F1];   // W1 fp16
__device__ __half g_w2h[F1 * F2];   // W2 fp16
__device__ __half g_h1[NN * F1];    // x @ W1   (fp16 gather table)
__device__ __half g_z1[NN * F1];    // layer1 output, fp16 (gemm2 A)
__device__ __half g_h2[NN * F2];    // z1 @ W2  (fp16 gather table)
__device__ __half g_z2[NN * F2];    // layer2 output, fp16 (decode table)
__device__ float g_als1[NN * 4];
__device__ float g_ald1[NN * 4];
__device__ float g_als2[NN * 8];
__device__ float g_ald2[NN * 8];
__device__ int   g_cnt[NN];
__device__ int   g_off[NN];
__device__ int   g_csr[EE];
__device__ int   g_total;

// ---------------- fp16 converts (x, W1, W2) -------------------------------------
__device__ __forceinline__ void cvt8(const float* __restrict__ in,
                                     __half* __restrict__ out, int i8) {
    float4 a = *(const float4*)(in + i8);
    float4 b = *(const float4*)(in + i8 + 4);
    __half2 h[4] = {__floats2half2_rn(a.x, a.y), __floats2half2_rn(a.z, a.w),
                    __floats2half2_rn(b.x, b.y), __floats2half2_rn(b.z, b.w)};
    *(uint4*)(out + i8) = *(uint4*)h;
}

__global__ void cvt_kernel(const float* __restrict__ x,
                           const float* __restrict__ W1,
                           const float* __restrict__ W2) {
    const int NX = NN * F1 / 8;    // 100000
    const int NW1 = F1 * F1 / 8;   // 2048
    const int NW2 = F1 * F2 / 8;   // 4096
    int i = blockIdx.x * blockDim.x + threadIdx.x;
    if (i < NX) {
        cvt8(x, g_x16, i * 8);
    } else if (i < NX + NW1) {
        cvt8(W1, g_w1h, (i - NX) * 8);
    } else if (i < NX + NW1 + NW2) {
        cvt8(W2, g_w2h, (i - NX - NW1) * 8);
    }
}

// ---------------- CSR construction (side stream) --------------------------------
__global__ void hist_kernel(const int* __restrict__ dst) {
    int e = (blockIdx.x * blockDim.x + threadIdx.x) * 4;
    if (e >= EE) return;
    int4 d = *(const int4*)(dst + e);  // 4 independent atomics in flight
    atomicAdd(&g_cnt[d.x], 1);
    atomicAdd(&g_cnt[d.y], 1);
    atomicAdd(&g_cnt[d.z], 1);
    atomicAdd(&g_cnt[d.w], 1);
}

// Segment allocator: CSR segments need only be contiguous per node, not
// ordered — warp-scan + one atomicAdd per warp replaces a global scan.
__global__ void alloc_kernel() {
    int i = blockIdx.x * blockDim.x + threadIdx.x;
    int lane = threadIdx.x & 31;
    int v = (i < NN) ? g_cnt[i] : 0;
    int s = v;
#pragma unroll
    for (int o = 1; o < 32; o <<= 1) {
        int t = __shfl_up_sync(0xffffffffu, s, o);
        if (lane >= o) s += t;
    }
    int total = __shfl_sync(0xffffffffu, s, 31);
    int base = 0;
    if (lane == 31) base = atomicAdd(&g_total, total);
    base = __shfl_sync(0xffffffffu, base, 31);
    if (i < NN) g_off[i] = base + s - v;
}

// scatter bumps g_off directly; afterwards g_off[d] = segment END.
// Consumers recompute start = g_off[d] - g_cnt[d]. 4 edges per thread for MLP.
__global__ void scatter_kernel(const int* __restrict__ src,
                               const int* __restrict__ dst) {
    int e = (blockIdx.x * blockDim.x + threadIdx.x) * 4;
    if (e >= EE) return;
    int4 s4 = *(const int4*)(src + e);
    int4 d4 = *(const int4*)(dst + e);
    int p0 = atomicAdd(&g_off[d4.x], 1);
    int p1 = atomicAdd(&g_off[d4.y], 1);
    int p2 = atomicAdd(&g_off[d4.z], 1);
    int p3 = atomicAdd(&g_off[d4.w], 1);
    g_csr[p0] = s4.x;
    g_csr[p1] = s4.y;
    g_csr[p2] = s4.z;
    g_csr[p3] = s4.w;
}

// ---------------- cp.async helper ----------------------------------------------
__device__ __forceinline__ void cpa16(void* s, const void* g) {
    unsigned int sa = (unsigned int)__cvta_generic_to_shared(s);
    asm volatile("cp.async.cg.shared.global [%0], [%1], 16;" ::"r"(sa), "l"(g));
}

// ---------------- GEMM via tensor cores + fused attention coefficients ---------
// Ch[rowOff+.., M] = half(A @ B); als/ald fused in epilogue. Row-offset param
// lets layer-2 run as two halves pipelined against agg1.
// fp16 in, fp32 accumulate. Block tile 128x128, 8 warps (4x2), warp 32x64.
// cp.async double-buffered mainloop; OOB A rows index-clamped (discarded).
#define AS_STRIDE 40
#define BS_STRIDE 136
#define BS_OFF (2 * 128 * AS_STRIDE * 2)  // bytes, after double-buffered A
__global__ __launch_bounds__(256) void gemm_wmma(const __half* __restrict__ A,
                                                 const __half* __restrict__ B,
                                                 __half* __restrict__ C,
                                                 const float* __restrict__ a_s,
                                                 const float* __restrict__ a_d,
                                                 float* __restrict__ als,
                                                 float* __restrict__ ald,
                                                 int rowOff, int n, int M) {
    __shared__ __align__(16) char smem_raw[38016];
    __half (*As)[AS_STRIDE] = (__half(*)[AS_STRIDE])smem_raw;     // [2*128][40]
    __half (*Bs)[BS_STRIDE] = (__half(*)[BS_STRIDE])(smem_raw + BS_OFF); // [2*32][136]

    int tid = threadIdx.x;
    int w = tid >> 5, lane = tid & 31;
    int wr = w >> 1, wc = w & 1;  // 4x2 warp grid -> warp tile 32(r) x 64(c)
    int rowBase = rowOff + blockIdx.x * 128, colBase = blockIdx.y * 128;

    wmma::fragment<wmma::accumulator, 16, 16, 16, float> acc[2][4];
#pragma unroll
    for (int i = 0; i < 2; i++)
#pragma unroll
        for (int j = 0; j < 4; j++) wmma::fill_fragment(acc[i][j], 0.f);

    auto stage = [&](int kt, int buf) {
#pragma unroll
        for (int c = tid; c < 512; c += 256) {
            int r = c >> 2, q = c & 3;
            int gr = min(rowBase + r, n - 1);  // clamp: OOB rows are discarded
            cpa16(&As[buf * 128 + r][q * 8],
                  A + (size_t)gr * 128 + kt * 32 + q * 8);
        }
#pragma unroll
        for (int c = tid; c < 512; c += 256) {
            int r = c >> 4, q = c & 15;
            cpa16(&Bs[buf * 32 + r][q * 8],
                  B + (size_t)(kt * 32 + r) * M + colBase + q * 8);
        }
        asm volatile("cp.async.commit_group;");
    };

    stage(0, 0);
    const int NT = 4;  // K = 128 / BK = 32
    for (int kt = 0; kt < NT; kt++) {
        int buf = kt & 1;
        asm volatile("cp.async.wait_group 0;");
        __syncthreads();
        if (kt + 1 < NT) stage(kt + 1, buf ^ 1);  // overlap with MMA below
#pragma unroll
        for (int kk = 0; kk < 32; kk += 16) {
            wmma::fragment<wmma::matrix_a, 16, 16, 16, __half, wmma::row_major> af[2];
            wmma::fragment<wmma::matrix_b, 16, 16, 16, __half, wmma::row_major> bf[4];
#pragma unroll
            for (int i = 0; i < 2; i++)
                wmma::load_matrix_sync(
                    af[i], &As[buf * 128 + wr * 32 + i * 16][kk], AS_STRIDE);
#pragma unroll
            for (int j = 0; j < 4; j++)
                wmma::load_matrix_sync(
                    bf[j], &Bs[buf * 32 + kk][wc * 64 + j * 16], BS_STRIDE);
#pragma unroll
            for (int i = 0; i < 2; i++)
#pragma unroll
                for (int j = 0; j < 4; j++)
                    wmma::mma_sync(acc[i][j], af[i], bf[j], acc[i][j]);
        }
    }
    __syncthreads();  // smem reuse below

    // epilogue: two 32x32 passes per warp via smem staging (4608B per warp)
    float (*Cs)[36] = (float(*)[36])(smem_raw + (size_t)w * 32 * 36 * 4);
    int row = rowBase + wr * 32 + lane;
#pragma unroll
    for (int jh = 0; jh < 2; jh++) {
#pragma unroll
        for (int i = 0; i < 2; i++)
#pragma unroll
            for (int j = 0; j < 2; j++)
                wmma::store_matrix_sync(&Cs[i * 16][j * 16], acc[i][jh * 2 + j],
                                        36, wmma::mem_row_major);
        __syncwarp();
        if (row < n) {
            float vals[32];
#pragma unroll
            for (int q = 0; q < 8; q++)
                *(float4*)&vals[q * 4] = *(const float4*)&Cs[lane][q * 4];

            __half2 hh[16];
#pragma unroll
            for (int t = 0; t < 16; t++)
                hh[t] = __floats2half2_rn(vals[2 * t], vals[2 * t + 1]);
            __half* cp = C + (size_t)row * M + colBase + wc * 64 + jh * 32;
            *(uint4*)(cp + 0)  = *(uint4*)&hh[0];
            *(uint4*)(cp + 8)  = *(uint4*)&hh[4];
            *(uint4*)(cp + 16) = *(uint4*)&hh[8];
            *(uint4*)(cp + 24) = *(uint4*)&hh[12];

            int head = (colBase + wc * 64 + jh * 32) >> 5;
            const float* asv = a_s + head * 32;
            const float* adv = a_d + head * 32;
            float sv = 0.f, dv = 0.f;
#pragma unroll
            for (int c = 0; c < 32; c++) {
                sv = fmaf(vals[c], asv[c], sv);
                dv = fmaf(vals[c], adv[c], dv);
            }
            int heads = M >> 5;
            als[row * heads + head] = sv;
            ald[row * heads + head] = dv;
        }
        __syncwarp();
    }
}

// ---------------- fused GAT aggregation: one warp per destination node ---------
// exp without max subtraction (softmax is shift-invariant; max is detached in
// the reference, logits are O(±5), so this is numerically safe at 1e-3).
// Features gathered in fp16 (single vector load), accumulated in fp32.
// [nodeBase, nodeLim) range allows pipelining agg1 halves with gemm2 halves.
// CLEANUP=true (last layer): zero g_cnt/g_total for the next replay.
template <int HEADS, int W, bool RELU, bool CLEANUP>
__global__ __launch_bounds__(256) void agg_kernel(
    const __half* __restrict__ h, const float* __restrict__ als,
    const float* __restrict__ ald, const float* __restrict__ bias,
    __half* __restrict__ zout, int nodeBase, int nodeLim) {
    constexpr int V = W / 32;  // channels per lane (4 or 8)
    int node = nodeBase + ((blockIdx.x * blockDim.x + threadIdx.x) >> 5);
    int lane = threadIdx.x & 31;
    if (node >= nodeLim) return;
    int head = (lane * V) >> 5;  // lane owns V consecutive channels of one head
    float aldh = ald[node * HEADS + head];
    float acc[V] = {};
    float den = 0.f;

    auto doEdge = [&](int s) {
        float e = als[s * HEADS + head] + aldh;
        e = e > 0.f ? e : 0.2f * e;  // LeakyReLU(0.2)
        float ex = __expf(e);
        den += ex;
        const __half* p = h + (size_t)s * W + lane * V;
        __half2 hv[V / 2];
        if (V == 8)
            *(uint4*)hv = *(const uint4*)p;
        else
            *(uint2*)hv = *(const uint2*)p;
#pragma unroll
        for (int q = 0; q < V / 2; q++) {
            float2 f = __half22float2(hv[q]);
            acc[q * 2 + 0] += ex * f.x;
            acc[q * 2 + 1] += ex * f.y;
        }
    };

    doEdge(node);  // self loop (add_self_loops=True)

    int m = g_cnt[node];
    int start = g_off[node] - m;  // g_off holds segment end post-scatter
    if (CLEANUP && lane == 0) {
        g_cnt[node] = 0;  // leave counters clean for the next run
        if (node == 0) g_total = 0;
    }
    for (int j0 = 0; j0 < m; j0 += 32) {
        int myS = (j0 + lane < m) ? g_csr[start + j0 + lane] : 0;
        int lim = min(32, m - j0);
        for (int k = 0; k < lim; k++) {
            int s = __shfl_sync(0xffffffffu, myS, k);
            doEdge(s);
        }
    }

    float inv = 1.f / (den + 1e-16f);
    __half2 oh[V / 2];
#pragma unroll
    for (int q = 0; q < V / 2; q++) {
        float ox = acc[q * 2 + 0] * inv + bias[lane * V + q * 2 + 0];
        float oy = acc[q * 2 + 1] * inv + bias[lane * V + q * 2 + 1];
        if (RELU) {
            ox = fmaxf(ox, 0.f);
            oy = fmaxf(oy, 0.f);
        }
        oh[q] = __floats2half2_rn(ox, oy);
    }
    if (V == 8)
        *(uint4*)(zout + (size_t)node * W + lane * V) = *(uint4*)oh;
    else
        *(uint2*)(zout + (size_t)node * W + lane * V) = *(uint2*)oh;
}

// ---------------- decode: logits = sum(z2[a] * z2[b]), 2 edges per warp --------
__global__ __launch_bounds__(256) void decode_kernel(
    const int* __restrict__ pos, const int* __restrict__ neg,
    float* __restrict__ out) {
    int warp = (blockIdx.x * blockDim.x + threadIdx.x) >> 5;
    int lane = threadIdx.x & 31;
    int half = lane >> 4, l16 = lane & 15;
    int idx = warp * 2 + half;
    if (idx >= 2 * EDEC) return;
    int a, b;
    if (idx < EDEC) {
        a = pos[idx];
        b = pos[EDEC + idx];
    } else {
        int k = idx - EDEC;
        a = neg[k];
        b = neg[EDEC + k];
    }
    const __half* pa = g_z2 + (size_t)a * F2 + l16 * 16;
    const __half* pb = g_z2 + (size_t)b * F2 + l16 * 16;
    uint4 ra0 = *(const uint4*)pa, ra1 = *(const uint4*)(pa + 8);
    uint4 rb0 = *(const uint4*)pb, rb1 = *(const uint4*)(pb + 8);
    __half2* ha0 = (__half2*)&ra0;
    __half2* ha1 = (__half2*)&ra1;
    __half2* hb0 = (__half2*)&rb0;
    __half2* hb1 = (__half2*)&rb1;
    float s = 0.f;
#pragma unroll
    for (int q = 0; q < 4; q++) {
        float2 fa = __half22float2(ha0[q]);
        float2 fb = __half22float2(hb0[q]);
        s = fmaf(fa.x, fb.x, s);
        s = fmaf(fa.y, fb.y, s);
        fa = __half22float2(ha1[q]);
        fb = __half22float2(hb1[q]);
        s = fmaf(fa.x, fb.x, s);
        s = fmaf(fa.y, fb.y, s);
    }
#pragma unroll
    for (int o = 8; o; o >>= 1) s += __shfl_xor_sync(0xffffffffu, s, o);
    if (l16 == 0) out[idx] = s;
}

// ---------------- launch --------------------------------------------------------
extern "C" void kernel_launch(void* const* d_in, const int* in_sizes, int n_in,
                              void* d_out, int out_size) {
    const float* x   = (const float*)d_in[0];
    const int*   ei  = (const int*)d_in[1];
    const int*   pos = (const int*)d_in[2];
    const int*   neg = (const int*)d_in[3];
    const float* W1  = (const float*)d_in[4];
    const float* as1 = (const float*)d_in[5];
    const float* ad1 = (const float*)d_in[6];
    const float* b1  = (const float*)d_in[7];
    const float* W2  = (const float*)d_in[8];
    const float* as2 = (const float*)d_in[9];
    const float* ad2 = (const float*)d_in[10];
    const float* b2  = (const float*)d_in[11];
    float* out = (float*)d_out;

    __half *x16p, *w1hp, *w2hp, *h1p, *z1p, *h2p, *z2p;
    float *als1p, *ald1p, *als2p, *ald2p;
    cudaGetSymbolAddress((void**)&x16p, g_x16);
    cudaGetSymbolAddress((void**)&w1hp, g_w1h);
    cudaGetSymbolAddress((void**)&w2hp, g_w2h);
    cudaGetSymbolAddress((void**)&h1p, g_h1);
    cudaGetSymbolAddress((void**)&z1p, g_z1);
    cudaGetSymbolAddress((void**)&h2p, g_h2);
    cudaGetSymbolAddress((void**)&z2p, g_z2);
    cudaGetSymbolAddress((void**)&als1p, g_als1);
    cudaGetSymbolAddress((void**)&ald1p, g_ald1);
    cudaGetSymbolAddress((void**)&als2p, g_als2);
    cudaGetSymbolAddress((void**)&ald2p, g_ald2);

    // Side stream + events (created once on the first, uncaptured correctness
    // call; captured replays reuse the handles — captured WORK is identical).
    static cudaStream_t s1 = nullptr;
    static cudaEvent_t evFork = nullptr, evCsr = nullptr, evA1 = nullptr,
                       evA2 = nullptr, evG2 = nullptr;
    if (s1 == nullptr) {
        cudaStreamCreateWithFlags(&s1, cudaStreamNonBlocking);
        cudaEventCreateWithFlags(&evFork, cudaEventDisableTiming);
        cudaEventCreateWithFlags(&evCsr, cudaEventDisableTiming);
        cudaEventCreateWithFlags(&evA1, cudaEventDisableTiming);
        cudaEventCreateWithFlags(&evA2, cudaEventDisableTiming);
        cudaEventCreateWithFlags(&evG2, cudaEventDisableTiming);
    }

    const int TB = 256;
    const int CVT_THREADS = NN * F1 / 8 + F1 * F1 / 8 + F1 * F2 / 8;
    auto aggBlocks = [&](int lo, int hi) { return ((hi - lo) * 32 + TB - 1) / TB; };

    // Fork: full CSR chain (hist -> alloc -> scatter) on side stream.
    // Counters are zero at entry, so hist has no dependency on main work.
    cudaEventRecord(evFork, 0);
    cudaStreamWaitEvent(s1, evFork, 0);
    hist_kernel<<<(EE / 4 + TB - 1) / TB, TB, 0, s1>>>(ei + EE);
    alloc_kernel<<<(NN + TB - 1) / TB, TB, 0, s1>>>();
    scatter_kernel<<<(EE / 4 + TB - 1) / TB, TB, 0, s1>>>(ei, ei + EE);
    cudaEventRecord(evCsr, s1);

    // Main: fp16 converts, then layer-1 GEMM (overlapped with CSR build).
    cvt_kernel<<<(CVT_THREADS + TB - 1) / TB, TB>>>(x, W1, W2);
    gemm_wmma<<<dim3((NN + 127) / 128, F1 / 128), TB>>>(
        x16p, w1hp, h1p, as1, ad1, als1p, ald1p, 0, NN, F1);

    // Join CSR, then agg1 in two halves; gemm2 halves chase them on s1.
    cudaStreamWaitEvent(0, evCsr, 0);
    agg_kernel<4, F1, true, false><<<aggBlocks(0, SPLIT), TB>>>(
        h1p, als1p, ald1p, b1, z1p, 0, SPLIT);
    cudaEventRecord(evA1, 0);
    agg_kernel<4, F1, true, false><<<aggBlocks(SPLIT, NN), TB>>>(
        h1p, als1p, ald1p, b1, z1p, SPLIT, NN);
    cudaEventRecord(evA2, 0);

    cudaStreamWaitEvent(s1, evA1, 0);
    gemm_wmma<<<dim3(SPLIT / 128, F2 / 128), TB, 0, s1>>>(
        z1p, w2hp, h2p, as2, ad2, als2p, ald2p, 0, NN, F2);
    cudaStreamWaitEvent(s1, evA2, 0);
    gemm_wmma<<<dim3((NN - SPLIT + 127) / 128, F2 / 128), TB, 0, s1>>>(
        z1p, w2hp, h2p, as2, ad2, als2p, ald2p, SPLIT, NN, F2);
    cudaEventRecord(evG2, s1);

    // Layer-2 aggregation (cleans counters) + decode on main.
    cudaStreamWaitEvent(0, evG2, 0);
    agg_kernel<8, F2, false, true><<<aggBlocks(0, NN), TB>>>(
        h2p, als2p, ald2p, b2, z2p, 0, NN);
    decode_kernel<<<(EDEC * 32 + TB - 1) / TB, TB>>>(pos, neg, out);
}

// round 14
// speedup vs baseline: 1.0260x; 1.0260x over previous
#include <cuda_runtime.h>
#include <cuda_fp16.h>
#include <cstdint>
#include <mma.h>
using namespace nvcuda;

#define NN   50000
#define EE   800000
#define EDEC 100000
#define F1   128     // H1*HID
#define F2   256     // H2*HID

// ---------------- scratch (device globals: no allocation allowed) -------------
// Counter protocol: g_cnt and g_total are zero at kernel_launch entry (static
// init on first call; layer-2 agg_kernel re-zeroes them before exiting), so
// the histogram can run immediately at stream-fork time.
__device__ __half g_x16[NN * F1];   // x in fp16 (gemm1 A)
__device__ __half g_w1h[F1 * F1];   // W1 fp16
__device__ __half g_w2h[F1 * F2];   // W2 fp16
__device__ __half g_h1[NN * F1];    // x @ W1   (fp16 gather table)
__device__ __half g_z1[NN * F1];    // layer1 output, fp16 (gemm2 A)
__device__ __half g_h2[NN * F2];    // z1 @ W2  (fp16 gather table)
__device__ __half g_z2[NN * F2];    // layer2 output, fp16 (decode table)
__device__ float g_als1[NN * 4];
__device__ float g_ald1[NN * 4];
__device__ float g_als2[NN * 8];
__device__ float g_ald2[NN * 8];
__device__ int   g_cnt[NN];
__device__ int   g_off[NN];
__device__ int   g_csr[EE];
__device__ int   g_total;

// ---------------- fp16 converts (x, W1, W2) -------------------------------------
__device__ __forceinline__ void cvt8(const float* __restrict__ in,
                                     __half* __restrict__ out, int i8) {
    float4 a = *(const float4*)(in + i8);
    float4 b = *(const float4*)(in + i8 + 4);
    __half2 h[4] = {__floats2half2_rn(a.x, a.y), __floats2half2_rn(a.z, a.w),
                    __floats2half2_rn(b.x, b.y), __floats2half2_rn(b.z, b.w)};
    *(uint4*)(out + i8) = *(uint4*)h;
}

__global__ void cvt_kernel(const float* __restrict__ x,
                           const float* __restrict__ W1,
                           const float* __restrict__ W2) {
    const int NX = NN * F1 / 8;    // 100000
    const int NW1 = F1 * F1 / 8;   // 2048
    const int NW2 = F1 * F2 / 8;   // 4096
    int i = blockIdx.x * blockDim.x + threadIdx.x;
    if (i < NX) {
        cvt8(x, g_x16, i * 8);
    } else if (i < NX + NW1) {
        cvt8(W1, g_w1h, (i - NX) * 8);
    } else if (i < NX + NW1 + NW2) {
        cvt8(W2, g_w2h, (i - NX - NW1) * 8);
    }
}

// ---------------- CSR construction (side stream) --------------------------------
__global__ void hist_kernel(const int* __restrict__ dst) {
    int e = (blockIdx.x * blockDim.x + threadIdx.x) * 4;
    if (e >= EE) return;
    int4 d = *(const int4*)(dst + e);  // 4 independent atomics in flight
    atomicAdd(&g_cnt[d.x], 1);
    atomicAdd(&g_cnt[d.y], 1);
    atomicAdd(&g_cnt[d.z], 1);
    atomicAdd(&g_cnt[d.w], 1);
}

// Segment allocator: CSR segments need only be contiguous per node, not
// ordered — warp-scan + one atomicAdd per warp replaces a global scan.
__global__ void alloc_kernel() {
    int i = blockIdx.x * blockDim.x + threadIdx.x;
    int lane = threadIdx.x & 31;
    int v = (i < NN) ? g_cnt[i] : 0;
    int s = v;
#pragma unroll
    for (int o = 1; o < 32; o <<= 1) {
        int t = __shfl_up_sync(0xffffffffu, s, o);
        if (lane >= o) s += t;
    }
    int total = __shfl_sync(0xffffffffu, s, 31);
    int base = 0;
    if (lane == 31) base = atomicAdd(&g_total, total);
    base = __shfl_sync(0xffffffffu, base, 31);
    if (i < NN) g_off[i] = base + s - v;
}

// scatter bumps g_off directly; afterwards g_off[d] = segment END.
// Consumers recompute start = g_off[d] - g_cnt[d]. 4 edges per thread for MLP.
__global__ void scatter_kernel(const int* __restrict__ src,
                               const int* __restrict__ dst) {
    int e = (blockIdx.x * blockDim.x + threadIdx.x) * 4;
    if (e >= EE) return;
    int4 s4 = *(const int4*)(src + e);
    int4 d4 = *(const int4*)(dst + e);
    int p0 = atomicAdd(&g_off[d4.x], 1);
    int p1 = atomicAdd(&g_off[d4.y], 1);
    int p2 = atomicAdd(&g_off[d4.z], 1);
    int p3 = atomicAdd(&g_off[d4.w], 1);
    g_csr[p0] = s4.x;
    g_csr[p1] = s4.y;
    g_csr[p2] = s4.z;
    g_csr[p3] = s4.w;
}

// ---------------- cp.async helper ----------------------------------------------
__device__ __forceinline__ void cpa16(void* s, const void* g) {
    unsigned int sa = (unsigned int)__cvta_generic_to_shared(s);
    asm volatile("cp.async.cg.shared.global [%0], [%1], 16;" ::"r"(sa), "l"(g));
}

// ---------------- GEMM via tensor cores + fused attention coefficients ---------
// Ch[n,M] = half(A[n,128] @ B[128,M]); als/ald[n,M/32] fused in epilogue.
// fp16 in, fp32 accumulate. Block tile 128x128, 8 warps (4x2), warp 32x64.
// cp.async double-buffered mainloop; OOB A rows index-clamped (discarded).
#define AS_STRIDE 40
#define BS_STRIDE 136
#define BS_OFF (2 * 128 * AS_STRIDE * 2)  // bytes, after double-buffered A
__global__ __launch_bounds__(256) void gemm_wmma(const __half* __restrict__ A,
                                                 const __half* __restrict__ B,
                                                 __half* __restrict__ C,
                                                 const float* __restrict__ a_s,
                                                 const float* __restrict__ a_d,
                                                 float* __restrict__ als,
                                                 float* __restrict__ ald,
                                                 int n, int M) {
    __shared__ __align__(16) char smem_raw[38016];
    __half (*As)[AS_STRIDE] = (__half(*)[AS_STRIDE])smem_raw;     // [2*128][40]
    __half (*Bs)[BS_STRIDE] = (__half(*)[BS_STRIDE])(smem_raw + BS_OFF); // [2*32][136]

    int tid = threadIdx.x;
    int w = tid >> 5, lane = tid & 31;
    int wr = w >> 1, wc = w & 1;  // 4x2 warp grid -> warp tile 32(r) x 64(c)
    int rowBase = blockIdx.x * 128, colBase = blockIdx.y * 128;

    wmma::fragment<wmma::accumulator, 16, 16, 16, float> acc[2][4];
#pragma unroll
    for (int i = 0; i < 2; i++)
#pragma unroll
        for (int j = 0; j < 4; j++) wmma::fill_fragment(acc[i][j], 0.f);

    auto stage = [&](int kt, int buf) {
#pragma unroll
        for (int c = tid; c < 512; c += 256) {
            int r = c >> 2, q = c & 3;
            int gr = min(rowBase + r, n - 1);  // clamp: OOB rows are discarded
            cpa16(&As[buf * 128 + r][q * 8],
                  A + (size_t)gr * 128 + kt * 32 + q * 8);
        }
#pragma unroll
        for (int c = tid; c < 512; c += 256) {
            int r = c >> 4, q = c & 15;
            cpa16(&Bs[buf * 32 + r][q * 8],
                  B + (size_t)(kt * 32 + r) * M + colBase + q * 8);
        }
        asm volatile("cp.async.commit_group;");
    };

    stage(0, 0);
    const int NT = 4;  // K = 128 / BK = 32
    for (int kt = 0; kt < NT; kt++) {
        int buf = kt & 1;
        asm volatile("cp.async.wait_group 0;");
        __syncthreads();
        if (kt + 1 < NT) stage(kt + 1, buf ^ 1);  // overlap with MMA below
#pragma unroll
        for (int kk = 0; kk < 32; kk += 16) {
            wmma::fragment<wmma::matrix_a, 16, 16, 16, __half, wmma::row_major> af[2];
            wmma::fragment<wmma::matrix_b, 16, 16, 16, __half, wmma::row_major> bf[4];
#pragma unroll
            for (int i = 0; i < 2; i++)
                wmma::load_matrix_sync(
                    af[i], &As[buf * 128 + wr * 32 + i * 16][kk], AS_STRIDE);
#pragma unroll
            for (int j = 0; j < 4; j++)
                wmma::load_matrix_sync(
                    bf[j], &Bs[buf * 32 + kk][wc * 64 + j * 16], BS_STRIDE);
#pragma unroll
            for (int i = 0; i < 2; i++)
#pragma unroll
                for (int j = 0; j < 4; j++)
                    wmma::mma_sync(acc[i][j], af[i], bf[j], acc[i][j]);
        }
    }
    __syncthreads();  // smem reuse below

    // epilogue: two 32x32 passes per warp via smem staging (4608B per warp)
    float (*Cs)[36] = (float(*)[36])(smem_raw + (size_t)w * 32 * 36 * 4);
    int row = rowBase + wr * 32 + lane;
#pragma unroll
    for (int jh = 0; jh < 2; jh++) {
#pragma unroll
        for (int i = 0; i < 2; i++)
#pragma unroll
            for (int j = 0; j < 2; j++)
                wmma::store_matrix_sync(&Cs[i * 16][j * 16], acc[i][jh * 2 + j],
                                        36, wmma::mem_row_major);
        __syncwarp();
        if (row < n) {
            float vals[32];
#pragma unroll
            for (int q = 0; q < 8; q++)
                *(float4*)&vals[q * 4] = *(const float4*)&Cs[lane][q * 4];

            __half2 hh[16];
#pragma unroll
            for (int t = 0; t < 16; t++)
                hh[t] = __floats2half2_rn(vals[2 * t], vals[2 * t + 1]);
            __half* cp = C + (size_t)row * M + colBase + wc * 64 + jh * 32;
            *(uint4*)(cp + 0)  = *(uint4*)&hh[0];
            *(uint4*)(cp + 8)  = *(uint4*)&hh[4];
            *(uint4*)(cp + 16) = *(uint4*)&hh[8];
            *(uint4*)(cp + 24) = *(uint4*)&hh[12];

            int head = (colBase + wc * 64 + jh * 32) >> 5;
            const float* asv = a_s + head * 32;
            const float* adv = a_d + head * 32;
            float sv = 0.f, dv = 0.f;
#pragma unroll
            for (int c = 0; c < 32; c++) {
                sv = fmaf(vals[c], asv[c], sv);
                dv = fmaf(vals[c], adv[c], dv);
            }
            int heads = M >> 5;
            als[row * heads + head] = sv;
            ald[row * heads + head] = dv;
        }
        __syncwarp();
    }
}

// ---------------- fused GAT aggregation: one warp per destination node ---------
// exp without max subtraction (softmax is shift-invariant; max is detached in
// the reference, logits are O(±5), so this is numerically safe at 1e-3).
// Features gathered in fp16 (single vector load), accumulated in fp32.
// CLEANUP=true (last layer): zero g_cnt/g_total for the next replay.
template <int HEADS, int W, bool RELU, bool CLEANUP>
__global__ __launch_bounds__(256) void agg_kernel(
    const __half* __restrict__ h, const float* __restrict__ als,
    const float* __restrict__ ald, const float* __restrict__ bias,
    __half* __restrict__ zout) {
    constexpr int V = W / 32;  // channels per lane (4 or 8)
    int node = (blockIdx.x * blockDim.x + threadIdx.x) >> 5;
    int lane = threadIdx.x & 31;
    if (node >= NN) return;
    int head = (lane * V) >> 5;  // lane owns V consecutive channels of one head
    float aldh = ald[node * HEADS + head];
    float acc[V] = {};
    float den = 0.f;

    auto doEdge = [&](int s) {
        float e = als[s * HEADS + head] + aldh;
        e = e > 0.f ? e : 0.2f * e;  // LeakyReLU(0.2)
        float ex = __expf(e);
        den += ex;
        const __half* p = h + (size_t)s * W + lane * V;
        __half2 hv[V / 2];
        if (V == 8)
            *(uint4*)hv = *(const uint4*)p;
        else
            *(uint2*)hv = *(const uint2*)p;
#pragma unroll
        for (int q = 0; q < V / 2; q++) {
            float2 f = __half22float2(hv[q]);
            acc[q * 2 + 0] += ex * f.x;
            acc[q * 2 + 1] += ex * f.y;
        }
    };

    doEdge(node);  // self loop (add_self_loops=True)

    int m = g_cnt[node];
    int start = g_off[node] - m;  // g_off holds segment end post-scatter
    if (CLEANUP && lane == 0) {
        g_cnt[node] = 0;  // leave counters clean for the next run
        if (node == 0) g_total = 0;
    }
    for (int j0 = 0; j0 < m; j0 += 32) {
        int myS = (j0 + lane < m) ? g_csr[start + j0 + lane] : 0;
        int lim = min(32, m - j0);
        for (int k = 0; k < lim; k++) {
            int s = __shfl_sync(0xffffffffu, myS, k);
            doEdge(s);
        }
    }

    float inv = 1.f / (den + 1e-16f);
    __half2 oh[V / 2];
#pragma unroll
    for (int q = 0; q < V / 2; q++) {
        float ox = acc[q * 2 + 0] * inv + bias[lane * V + q * 2 + 0];
        float oy = acc[q * 2 + 1] * inv + bias[lane * V + q * 2 + 1];
        if (RELU) {
            ox = fmaxf(ox, 0.f);
            oy = fmaxf(oy, 0.f);
        }
        oh[q] = __floats2half2_rn(ox, oy);
    }
    if (V == 8)
        *(uint4*)(zout + (size_t)node * W + lane * V) = *(uint4*)oh;
    else
        *(uint2*)(zout + (size_t)node * W + lane * V) = *(uint2*)oh;
}

// ---------------- decode: logits = sum(z2[a] * z2[b]), 2 edges per warp --------
__global__ __launch_bounds__(256) void decode_kernel(
    const int* __restrict__ pos, const int* __restrict__ neg,
    float* __restrict__ out) {
    int warp = (blockIdx.x * blockDim.x + threadIdx.x) >> 5;
    int lane = threadIdx.x & 31;
    int half = lane >> 4, l16 = lane & 15;
    int idx = warp * 2 + half;
    if (idx >= 2 * EDEC) return;
    int a, b;
    if (idx < EDEC) {
        a = pos[idx];
        b = pos[EDEC + idx];
    } else {
        int k = idx - EDEC;
        a = neg[k];
        b = neg[EDEC + k];
    }
    const __half* pa = g_z2 + (size_t)a * F2 + l16 * 16;
    const __half* pb = g_z2 + (size_t)b * F2 + l16 * 16;
    uint4 ra0 = *(const uint4*)pa, ra1 = *(const uint4*)(pa + 8);
    uint4 rb0 = *(const uint4*)pb, rb1 = *(const uint4*)(pb + 8);
    __half2* ha0 = (__half2*)&ra0;
    __half2* ha1 = (__half2*)&ra1;
    __half2* hb0 = (__half2*)&rb0;
    __half2* hb1 = (__half2*)&rb1;
    float s = 0.f;
#pragma unroll
    for (int q = 0; q < 4; q++) {
        float2 fa = __half22float2(ha0[q]);
        float2 fb = __half22float2(hb0[q]);
        s = fmaf(fa.x, fb.x, s);
        s = fmaf(fa.y, fb.y, s);
        fa = __half22float2(ha1[q]);
        fb = __half22float2(hb1[q]);
        s = fmaf(fa.x, fb.x, s);
        s = fmaf(fa.y, fb.y, s);
    }
#pragma unroll
    for (int o = 8; o; o >>= 1) s += __shfl_xor_sync(0xffffffffu, s, o);
    if (l16 == 0) out[idx] = s;
}

// ---------------- launch --------------------------------------------------------
extern "C" void kernel_launch(void* const* d_in, const int* in_sizes, int n_in,
                              void* d_out, int out_size) {
    const float* x   = (const float*)d_in[0];
    const int*   ei  = (const int*)d_in[1];
    const int*   pos = (const int*)d_in[2];
    const int*   neg = (const int*)d_in[3];
    const float* W1  = (const float*)d_in[4];
    const float* as1 = (const float*)d_in[5];
    const float* ad1 = (const float*)d_in[6];
    const float* b1  = (const float*)d_in[7];
    const float* W2  = (const float*)d_in[8];
    const float* as2 = (const float*)d_in[9];
    const float* ad2 = (const float*)d_in[10];
    const float* b2  = (const float*)d_in[11];
    float* out = (float*)d_out;

    __half *x16p, *w1hp, *w2hp, *h1p, *z1p, *h2p, *z2p;
    float *als1p, *ald1p, *als2p, *ald2p;
    cudaGetSymbolAddress((void**)&x16p, g_x16);
    cudaGetSymbolAddress((void**)&w1hp, g_w1h);
    cudaGetSymbolAddress((void**)&w2hp, g_w2h);
    cudaGetSymbolAddress((void**)&h1p, g_h1);
    cudaGetSymbolAddress((void**)&z1p, g_z1);
    cudaGetSymbolAddress((void**)&h2p, g_h2);
    cudaGetSymbolAddress((void**)&z2p, g_z2);
    cudaGetSymbolAddress((void**)&als1p, g_als1);
    cudaGetSymbolAddress((void**)&ald1p, g_ald1);
    cudaGetSymbolAddress((void**)&als2p, g_als2);
    cudaGetSymbolAddress((void**)&ald2p, g_ald2);

    // Side stream + events (created once on the first, uncaptured correctness
    // call; captured replays reuse the handles — captured WORK is identical).
    static cudaStream_t s1 = nullptr;
    static cudaEvent_t evFork = nullptr, evCsr = nullptr;
    if (s1 == nullptr) {
        cudaStreamCreateWithFlags(&s1, cudaStreamNonBlocking);
        cudaEventCreateWithFlags(&evFork, cudaEventDisableTiming);
        cudaEventCreateWithFlags(&evCsr, cudaEventDisableTiming);
    }

    const int TB = 256;
    int nodeWarpBlocks = (NN * 32 + TB - 1) / TB;  // 6250
    const int CVT_THREADS = NN * F1 / 8 + F1 * F1 / 8 + F1 * F2 / 8;

    // Fork: full CSR chain (hist -> alloc -> scatter) on side stream.
    // Counters are zero at entry, so hist has no dependency on main work.
    // These kernels are atomic-latency-bound (issue < 5%), so they coexist
    // with the main stream's cvt+gemm1 without stealing meaningful SM time.
    cudaEventRecord(evFork, 0);
    cudaStreamWaitEvent(s1, evFork, 0);
    hist_kernel<<<(EE / 4 + TB - 1) / TB, TB, 0, s1>>>(ei + EE);
    alloc_kernel<<<(NN + TB - 1) / TB, TB, 0, s1>>>();
    scatter_kernel<<<(EE / 4 + TB - 1) / TB, TB, 0, s1>>>(ei, ei + EE);
    cudaEventRecord(evCsr, s1);

    // Main: fp16 converts, then layer-1 GEMM (overlapped with CSR build).
    cvt_kernel<<<(CVT_THREADS + TB - 1) / TB, TB>>>(x, W1, W2);
    gemm_wmma<<<dim3((NN + 127) / 128, F1 / 128), TB>>>(
        x16p, w1hp, h1p, as1, ad1, als1p, ald1p, NN, F1);

    // Join: agg1 needs both gemm1 (main) and the CSR build (s1).
    cudaStreamWaitEvent(0, evCsr, 0);
    agg_kernel<4, F1, true, false><<<nodeWarpBlocks, TB>>>(
        h1p, als1p, ald1p, b1, z1p);

    // Layer 2 (cleans counters for next run)
    gemm_wmma<<<dim3((NN + 127) / 128, F2 / 128), TB>>>(
        z1p, w2hp, h2p, as2, ad2, als2p, ald2p, NN, F2);
    agg_kernel<8, F2, false, true><<<nodeWarpBlocks, TB>>>(
        h2p, als2p, ald2p, b2, z2p);

    // Decode
    decode_kernel<<<(EDEC * 32 + TB - 1) / TB, TB>>>(pos, neg, out);
}

// round 15
// speedup vs baseline: 1.0275x; 1.0014x over previous
#include <cuda_runtime.h>
#include <cuda_fp16.h>
#include <cstdint>
#include <mma.h>
using namespace nvcuda;

#define NN   50000
#define EE   800000
#define EDEC 100000
#define F1   128     // H1*HID
#define F2   256     // H2*HID

// ---------------- scratch (device globals: no allocation allowed) -------------
// Counter protocol: g_cnt and g_total are zero at kernel_launch entry (static
// init on first call; layer-2 agg_kernel re-zeroes them before exiting), so
// the histogram can run immediately at stream-fork time.
__device__ __half g_w1h[F1 * F1];   // W1 fp16
__device__ __half g_w2h[F1 * F2];   // W2 fp16
__device__ __half g_h1[NN * F1];    // x @ W1   (fp16 gather table)
__device__ __half g_z1[NN * F1];    // layer1 output, fp16 (gemm2 A)
__device__ __half g_h2[NN * F2];    // z1 @ W2  (fp16 gather table)
__device__ __half g_z2[NN * F2];    // layer2 output, fp16 (decode table)
__device__ float g_als1[NN * 4];
__device__ float g_ald1[NN * 4];
__device__ float g_als2[NN * 8];
__device__ float g_ald2[NN * 8];
__device__ int   g_cnt[NN];
__device__ int   g_off[NN];
__device__ int   g_csr[EE];
__device__ int   g_total;

// ---------------- fp16 converts (W1, W2 only; x folded into gemm1) -------------
__device__ __forceinline__ void cvt8(const float* __restrict__ in,
                                     __half* __restrict__ out, int i8) {
    float4 a = *(const float4*)(in + i8);
    float4 b = *(const float4*)(in + i8 + 4);
    __half2 h[4] = {__floats2half2_rn(a.x, a.y), __floats2half2_rn(a.z, a.w),
                    __floats2half2_rn(b.x, b.y), __floats2half2_rn(b.z, b.w)};
    *(uint4*)(out + i8) = *(uint4*)h;
}

__global__ void cvt_kernel(const float* __restrict__ W1,
                           const float* __restrict__ W2) {
    const int NW1 = F1 * F1 / 8;   // 2048
    const int NW2 = F1 * F2 / 8;   // 4096
    int i = blockIdx.x * blockDim.x + threadIdx.x;
    if (i < NW1) {
        cvt8(W1, g_w1h, i * 8);
    } else if (i < NW1 + NW2) {
        cvt8(W2, g_w2h, (i - NW1) * 8);
    }
}

// ---------------- CSR construction (side stream) --------------------------------
__global__ void hist_kernel(const int* __restrict__ dst) {
    int e = (blockIdx.x * blockDim.x + threadIdx.x) * 4;
    if (e >= EE) return;
    int4 d = *(const int4*)(dst + e);  // 4 independent atomics in flight
    atomicAdd(&g_cnt[d.x], 1);
    atomicAdd(&g_cnt[d.y], 1);
    atomicAdd(&g_cnt[d.z], 1);
    atomicAdd(&g_cnt[d.w], 1);
}

// Segment allocator: CSR segments need only be contiguous per node, not
// ordered — warp-scan + one atomicAdd per warp replaces a global scan.
__global__ void alloc_kernel() {
    int i = blockIdx.x * blockDim.x + threadIdx.x;
    int lane = threadIdx.x & 31;
    int v = (i < NN) ? g_cnt[i] : 0;
    int s = v;
#pragma unroll
    for (int o = 1; o < 32; o <<= 1) {
        int t = __shfl_up_sync(0xffffffffu, s, o);
        if (lane >= o) s += t;
    }
    int total = __shfl_sync(0xffffffffu, s, 31);
    int base = 0;
    if (lane == 31) base = atomicAdd(&g_total, total);
    base = __shfl_sync(0xffffffffu, base, 31);
    if (i < NN) g_off[i] = base + s - v;
}

// scatter bumps g_off directly; afterwards g_off[d] = segment END.
// Consumers recompute start = g_off[d] - g_cnt[d]. 4 edges per thread for MLP.
__global__ void scatter_kernel(const int* __restrict__ src,
                               const int* __restrict__ dst) {
    int e = (blockIdx.x * blockDim.x + threadIdx.x) * 4;
    if (e >= EE) return;
    int4 s4 = *(const int4*)(src + e);
    int4 d4 = *(const int4*)(dst + e);
    int p0 = atomicAdd(&g_off[d4.x], 1);
    int p1 = atomicAdd(&g_off[d4.y], 1);
    int p2 = atomicAdd(&g_off[d4.z], 1);
    int p3 = atomicAdd(&g_off[d4.w], 1);
    g_csr[p0] = s4.x;
    g_csr[p1] = s4.y;
    g_csr[p2] = s4.z;
    g_csr[p3] = s4.w;
}

// ---------------- cp.async helper ----------------------------------------------
__device__ __forceinline__ void cpa16(void* s, const void* g) {
    unsigned int sa = (unsigned int)__cvta_generic_to_shared(s);
    asm volatile("cp.async.cg.shared.global [%0], [%1], 16;" ::"r"(sa), "l"(g));
}

// ---------------- GEMM via tensor cores + fused attention coefficients ---------
// Ch[n,M] = half(A[n,128] @ B[128,M]); als/ald[n,M/32] fused in epilogue.
// A32=true: A is fp32, converted to fp16 in-flight (register-staged LDG one
// tile ahead -> cvt -> STS); A32=false: A is fp16, staged via cp.async.
// B always cp.async. Block tile 128x128, 8 warps (4x2), warp 32x64.
// OOB A rows are index-clamped (their outputs are discarded, never stored).
#define AS_STRIDE 40
#define BS_STRIDE 136
#define BS_OFF (2 * 128 * AS_STRIDE * 2)  // bytes, after double-buffered A
template <bool A32>
__global__ __launch_bounds__(256) void gemm_wmma(const void* __restrict__ Av,
                                                 const __half* __restrict__ B,
                                                 __half* __restrict__ C,
                                                 const float* __restrict__ a_s,
                                                 const float* __restrict__ a_d,
                                                 float* __restrict__ als,
                                                 float* __restrict__ ald,
                                                 int n, int M) {
    __shared__ __align__(16) char smem_raw[38016];
    __half (*As)[AS_STRIDE] = (__half(*)[AS_STRIDE])smem_raw;     // [2*128][40]
    __half (*Bs)[BS_STRIDE] = (__half(*)[BS_STRIDE])(smem_raw + BS_OFF); // [2*32][136]

    const float* Af = (const float*)Av;
    const __half* Ah = (const __half*)Av;

    int tid = threadIdx.x;
    int w = tid >> 5, lane = tid & 31;
    int wr = w >> 1, wc = w & 1;  // 4x2 warp grid -> warp tile 32(r) x 64(c)
    int rowBase = blockIdx.x * 128, colBase = blockIdx.y * 128;

    wmma::fragment<wmma::accumulator, 16, 16, 16, float> acc[2][4];
#pragma unroll
    for (int i = 0; i < 2; i++)
#pragma unroll
        for (int j = 0; j < 4; j++) wmma::fill_fragment(acc[i][j], 0.f);

    float4 aregs[2][2];  // A32 path: 2 chunks x 8 floats, staged one tile ahead

    auto ldgA = [&](int kt) {  // A32: issue global loads for tile kt
#pragma unroll
        for (int t = 0; t < 2; t++) {
            int c = tid + t * 256;
            int r = c >> 2, q = c & 3;
            int gr = min(rowBase + r, n - 1);  // clamp: OOB rows discarded
            const float* src = Af + (size_t)gr * 128 + kt * 32 + q * 8;
            aregs[t][0] = *(const float4*)src;
            aregs[t][1] = *(const float4*)(src + 4);
        }
    };
    auto stsA = [&](int buf) {  // A32: convert staged regs, store to smem
#pragma unroll
        for (int t = 0; t < 2; t++) {
            int c = tid + t * 256;
            int r = c >> 2, q = c & 3;
            __half2 h[4] = {
                __floats2half2_rn(aregs[t][0].x, aregs[t][0].y),
                __floats2half2_rn(aregs[t][0].z, aregs[t][0].w),
                __floats2half2_rn(aregs[t][1].x, aregs[t][1].y),
                __floats2half2_rn(aregs[t][1].z, aregs[t][1].w)};
            *(uint4*)&As[buf * 128 + r][q * 8] = *(uint4*)h;
        }
    };
    auto cpaA = [&](int kt, int buf) {  // fp16 A path
#pragma unroll
        for (int c = tid; c < 512; c += 256) {
            int r = c >> 2, q = c & 3;
            int gr = min(rowBase + r, n - 1);
            cpa16(&As[buf * 128 + r][q * 8],
                  Ah + (size_t)gr * 128 + kt * 32 + q * 8);
        }
    };
    auto cpaB = [&](int kt, int buf) {
#pragma unroll
        for (int c = tid; c < 512; c += 256) {
            int r = c >> 4, q = c & 15;
            cpa16(&Bs[buf * 32 + r][q * 8],
                  B + (size_t)(kt * 32 + r) * M + colBase + q * 8);
        }
        asm volatile("cp.async.commit_group;");
    };

    // prologue: tile 0 in flight
    if (A32) ldgA(0); else cpaA(0, 0);
    cpaB(0, 0);

    const int NT = 4;  // K = 128 / BK = 32
    for (int kt = 0; kt < NT; kt++) {
        int buf = kt & 1;
        if (A32) stsA(buf);  // consume staged regs for tile kt
        asm volatile("cp.async.wait_group 0;");
        __syncthreads();
        if (kt + 1 < NT) {  // stage tile kt+1; latency hides under MMA below
            if (A32) ldgA(kt + 1); else cpaA(kt + 1, buf ^ 1);
            cpaB(kt + 1, buf ^ 1);
        }
#pragma unroll
        for (int kk = 0; kk < 32; kk += 16) {
            wmma::fragment<wmma::matrix_a, 16, 16, 16, __half, wmma::row_major> af[2];
            wmma::fragment<wmma::matrix_b, 16, 16, 16, __half, wmma::row_major> bf[4];
#pragma unroll
            for (int i = 0; i < 2; i++)
                wmma::load_matrix_sync(
                    af[i], &As[buf * 128 + wr * 32 + i * 16][kk], AS_STRIDE);
#pragma unroll
            for (int j = 0; j < 4; j++)
                wmma::load_matrix_sync(
                    bf[j], &Bs[buf * 32 + kk][wc * 64 + j * 16], BS_STRIDE);
#pragma unroll
            for (int i = 0; i < 2; i++)
#pragma unroll
                for (int j = 0; j < 4; j++)
                    wmma::mma_sync(acc[i][j], af[i], bf[j], acc[i][j]);
        }
    }
    __syncthreads();  // smem reuse below

    // epilogue: two 32x32 passes per warp via smem staging (4608B per warp)
    float (*Cs)[36] = (float(*)[36])(smem_raw + (size_t)w * 32 * 36 * 4);
    int row = rowBase + wr * 32 + lane;
#pragma unroll
    for (int jh = 0; jh < 2; jh++) {
#pragma unroll
        for (int i = 0; i < 2; i++)
#pragma unroll
            for (int j = 0; j < 2; j++)
                wmma::store_matrix_sync(&Cs[i * 16][j * 16], acc[i][jh * 2 + j],
                                        36, wmma::mem_row_major);
        __syncwarp();
        if (row < n) {
            float vals[32];
#pragma unroll
            for (int q = 0; q < 8; q++)
                *(float4*)&vals[q * 4] = *(const float4*)&Cs[lane][q * 4];

            __half2 hh[16];
#pragma unroll
            for (int t = 0; t < 16; t++)
                hh[t] = __floats2half2_rn(vals[2 * t], vals[2 * t + 1]);
            __half* cp = C + (size_t)row * M + colBase + wc * 64 + jh * 32;
            *(uint4*)(cp + 0)  = *(uint4*)&hh[0];
            *(uint4*)(cp + 8)  = *(uint4*)&hh[4];
            *(uint4*)(cp + 16) = *(uint4*)&hh[8];
            *(uint4*)(cp + 24) = *(uint4*)&hh[12];

            int head = (colBase + wc * 64 + jh * 32) >> 5;
            const float* asv = a_s + head * 32;
            const float* adv = a_d + head * 32;
            float sv = 0.f, dv = 0.f;
#pragma unroll
            for (int c = 0; c < 32; c++) {
                sv = fmaf(vals[c], asv[c], sv);
                dv = fmaf(vals[c], adv[c], dv);
            }
            int heads = M >> 5;
            als[row * heads + head] = sv;
            ald[row * heads + head] = dv;
        }
        __syncwarp();
    }
}

// ---------------- fused GAT aggregation: one warp per destination node ---------
// exp without max subtraction (softmax is shift-invariant; max is detached in
// the reference, logits are O(±5), so this is numerically safe at 1e-3).
// Features gathered in fp16 (single vector load), accumulated in fp32.
// CLEANUP=true (last layer): zero g_cnt/g_total for the next replay.
template <int HEADS, int W, bool RELU, bool CLEANUP>
__global__ __launch_bounds__(256) void agg_kernel(
    const __half* __restrict__ h, const float* __restrict__ als,
    const float* __restrict__ ald, const float* __restrict__ bias,
    __half* __restrict__ zout) {
    constexpr int V = W / 32;  // channels per lane (4 or 8)
    int node = (blockIdx.x * blockDim.x + threadIdx.x) >> 5;
    int lane = threadIdx.x & 31;
    if (node >= NN) return;
    int head = (lane * V) >> 5;  // lane owns V consecutive channels of one head
    float aldh = ald[node * HEADS + head];
    float acc[V] = {};
    float den = 0.f;

    auto doEdge = [&](int s) {
        float e = als[s * HEADS + head] + aldh;
        e = e > 0.f ? e : 0.2f * e;  // LeakyReLU(0.2)
        float ex = __expf(e);
        den += ex;
        const __half* p = h + (size_t)s * W + lane * V;
        __half2 hv[V / 2];
        if (V == 8)
            *(uint4*)hv = *(const uint4*)p;
        else
            *(uint2*)hv = *(const uint2*)p;
#pragma unroll
        for (int q = 0; q < V / 2; q++) {
            float2 f = __half22float2(hv[q]);
            acc[q * 2 + 0] += ex * f.x;
            acc[q * 2 + 1] += ex * f.y;
        }
    };

    doEdge(node);  // self loop (add_self_loops=True)

    int m = g_cnt[node];
    int start = g_off[node] - m;  // g_off holds segment end post-scatter
    if (CLEANUP && lane == 0) {
        g_cnt[node] = 0;  // leave counters clean for the next run
        if (node == 0) g_total = 0;
    }
    for (int j0 = 0; j0 < m; j0 += 32) {
        int myS = (j0 + lane < m) ? g_csr[start + j0 + lane] : 0;
        int lim = min(32, m - j0);
        for (int k = 0; k < lim; k++) {
            int s = __shfl_sync(0xffffffffu, myS, k);
            doEdge(s);
        }
    }

    float inv = 1.f / (den + 1e-16f);
    __half2 oh[V / 2];
#pragma unroll
    for (int q = 0; q < V / 2; q++) {
        float ox = acc[q * 2 + 0] * inv + bias[lane * V + q * 2 + 0];
        float oy = acc[q * 2 + 1] * inv + bias[lane * V + q * 2 + 1];
        if (RELU) {
            ox = fmaxf(ox, 0.f);
            oy = fmaxf(oy, 0.f);
        }
        oh[q] = __floats2half2_rn(ox, oy);
    }
    if (V == 8)
        *(uint4*)(zout + (size_t)node * W + lane * V) = *(uint4*)oh;
    else
        *(uint2*)(zout + (size_t)node * W + lane * V) = *(uint2*)oh;
}

// ---------------- decode: logits = sum(z2[a] * z2[b]), 2 edges per warp --------
__global__ __launch_bounds__(256) void decode_kernel(
    const int* __restrict__ pos, const int* __restrict__ neg,
    float* __restrict__ out) {
    int warp = (blockIdx.x * blockDim.x + threadIdx.x) >> 5;
    int lane = threadIdx.x & 31;
    int half = lane >> 4, l16 = lane & 15;
    int idx = warp * 2 + half;
    if (idx >= 2 * EDEC) return;
    int a, b;
    if (idx < EDEC) {
        a = pos[idx];
        b = pos[EDEC + idx];
    } else {
        int k = idx - EDEC;
        a = neg[k];
        b = neg[EDEC + k];
    }
    const __half* pa = g_z2 + (size_t)a * F2 + l16 * 16;
    const __half* pb = g_z2 + (size_t)b * F2 + l16 * 16;
    uint4 ra0 = *(const uint4*)pa, ra1 = *(const uint4*)(pa + 8);
    uint4 rb0 = *(const uint4*)pb, rb1 = *(const uint4*)(pb + 8);
    __half2* ha0 = (__half2*)&ra0;
    __half2* ha1 = (__half2*)&ra1;
    __half2* hb0 = (__half2*)&rb0;
    __half2* hb1 = (__half2*)&rb1;
    float s = 0.f;
#pragma unroll
    for (int q = 0; q < 4; q++) {
        float2 fa = __half22float2(ha0[q]);
        float2 fb = __half22float2(hb0[q]);
        s = fmaf(fa.x, fb.x, s);
        s = fmaf(fa.y, fb.y, s);
        fa = __half22float2(ha1[q]);
        fb = __half22float2(hb1[q]);
        s = fmaf(fa.x, fb.x, s);
        s = fmaf(fa.y, fb.y, s);
    }
#pragma unroll
    for (int o = 8; o; o >>= 1) s += __shfl_xor_sync(0xffffffffu, s, o);
    if (l16 == 0) out[idx] = s;
}

// ---------------- launch --------------------------------------------------------
extern "C" void kernel_launch(void* const* d_in, const int* in_sizes, int n_in,
                              void* d_out, int out_size) {
    const float* x   = (const float*)d_in[0];
    const int*   ei  = (const int*)d_in[1];
    const int*   pos = (const int*)d_in[2];
    const int*   neg = (const int*)d_in[3];
    const float* W1  = (const float*)d_in[4];
    const float* as1 = (const float*)d_in[5];
    const float* ad1 = (const float*)d_in[6];
    const float* b1  = (const float*)d_in[7];
    const float* W2  = (const float*)d_in[8];
    const float* as2 = (const float*)d_in[9];
    const float* ad2 = (const float*)d_in[10];
    const float* b2  = (const float*)d_in[11];
    float* out = (float*)d_out;

    __half *w1hp, *w2hp, *h1p, *z1p, *h2p, *z2p;
    float *als1p, *ald1p, *als2p, *ald2p;
    cudaGetSymbolAddress((void**)&w1hp, g_w1h);
    cudaGetSymbolAddress((void**)&w2hp, g_w2h);
    cudaGetSymbolAddress((void**)&h1p, g_h1);
    cudaGetSymbolAddress((void**)&z1p, g_z1);
    cudaGetSymbolAddress((void**)&h2p, g_h2);
    cudaGetSymbolAddress((void**)&z2p, g_z2);
    cudaGetSymbolAddress((void**)&als1p, g_als1);
    cudaGetSymbolAddress((void**)&ald1p, g_ald1);
    cudaGetSymbolAddress((void**)&als2p, g_als2);
    cudaGetSymbolAddress((void**)&ald2p, g_ald2);

    // Side stream + events (created once on the first, uncaptured correctness
    // call; captured replays reuse the handles — captured WORK is identical).
    static cudaStream_t s1 = nullptr;
    static cudaEvent_t evFork = nullptr, evCsr = nullptr;
    if (s1 == nullptr) {
        cudaStreamCreateWithFlags(&s1, cudaStreamNonBlocking);
        cudaEventCreateWithFlags(&evFork, cudaEventDisableTiming);
        cudaEventCreateWithFlags(&evCsr, cudaEventDisableTiming);
    }

    const int TB = 256;
    int nodeWarpBlocks = (NN * 32 + TB - 1) / TB;  // 6250
    const int CVT_THREADS = F1 * F1 / 8 + F1 * F2 / 8;  // W1+W2 only

    // Fork: full CSR chain (hist -> alloc -> scatter) on side stream.
    // Counters are zero at entry, so hist has no dependency on main work.
    cudaEventRecord(evFork, 0);
    cudaStreamWaitEvent(s1, evFork, 0);
    hist_kernel<<<(EE / 4 + TB - 1) / TB, TB, 0, s1>>>(ei + EE);
    alloc_kernel<<<(NN + TB - 1) / TB, TB, 0, s1>>>();
    scatter_kernel<<<(EE / 4 + TB - 1) / TB, TB, 0, s1>>>(ei, ei + EE);
    cudaEventRecord(evCsr, s1);

    // Main: weight converts (tiny), then layer-1 GEMM consuming fp32 x directly
    // (x conversion folded into the GEMM A-stage). Overlapped with CSR build.
    cvt_kernel<<<(CVT_THREADS + TB - 1) / TB, TB>>>(W1, W2);
    gemm_wmma<true><<<dim3((NN + 127) / 128, F1 / 128), TB>>>(
        x, w1hp, h1p, as1, ad1, als1p, ald1p, NN, F1);

    // Join: agg1 needs both gemm1 (main) and the CSR build (s1).
    cudaStreamWaitEvent(0, evCsr, 0);
    agg_kernel<4, F1, true, false><<<nodeWarpBlocks, TB>>>(
        h1p, als1p, ald1p, b1, z1p);

    // Layer 2 (cleans counters for next run)
    gemm_wmma<false><<<dim3((NN + 127) / 128, F2 / 128), TB>>>(
        z1p, w2hp, h2p, as2, ad2, als2p, ald2p, NN, F2);
    agg_kernel<8, F2, false, true><<<nodeWarpBlocks, TB>>>(
        h2p, als2p, ald2p, b2, z2p);

    // Decode
    decode_kernel<<<(EDEC * 32 + TB - 1) / TB, TB>>>(pos, neg, out);
}

// round 16
// speedup vs baseline: 1.0696x; 1.0410x over previous
#include <cuda_runtime.h>
#include <cuda_fp16.h>
#include <cstdint>
#include <mma.h>
using namespace nvcuda;

#define NN   50000
#define EE   800000
#define EDEC 100000
#define F1   128     // H1*HID
#define F2   256     // H2*HID

// ---------------- scratch (device globals: no allocation allowed) -------------
// Counter protocol: g_cnt and g_total are zero at kernel_launch entry (static
// init on first call; layer-2 agg_kernel re-zeroes them before exiting), so
// the histogram can run immediately at stream-fork time.
__device__ __half g_w1h[F1 * F1];   // W1 fp16
__device__ __half g_w2h[F1 * F2];   // W2 fp16
__device__ __half g_h1[NN * F1];    // x @ W1   (fp16 gather table)
__device__ __half g_z1[NN * F1];    // layer1 output, fp16 (gemm2 A)
__device__ __half g_h2[NN * F2];    // z1 @ W2  (fp16 gather table)
__device__ __half g_z2[NN * F2];    // layer2 output, fp16 (decode table)
__device__ float g_als1[NN * 4];
__device__ float g_ald1[NN * 4];
__device__ float g_als2[NN * 8];
__device__ float g_ald2[NN * 8];
__device__ int   g_cnt[NN];
__device__ int   g_off[NN];
__device__ int   g_csr[EE];
__device__ int   g_total;

// ---------------- fp16 converts (W1, W2 only; x folded into gemm1) -------------
__device__ __forceinline__ void cvt8(const float* __restrict__ in,
                                     __half* __restrict__ out, int i8) {
    float4 a = *(const float4*)(in + i8);
    float4 b = *(const float4*)(in + i8 + 4);
    __half2 h[4] = {__floats2half2_rn(a.x, a.y), __floats2half2_rn(a.z, a.w),
                    __floats2half2_rn(b.x, b.y), __floats2half2_rn(b.z, b.w)};
    *(uint4*)(out + i8) = *(uint4*)h;
}

__global__ void cvt_kernel(const float* __restrict__ W1,
                           const float* __restrict__ W2) {
    const int NW1 = F1 * F1 / 8;   // 2048
    const int NW2 = F1 * F2 / 8;   // 4096
    int i = blockIdx.x * blockDim.x + threadIdx.x;
    if (i < NW1) {
        cvt8(W1, g_w1h, i * 8);
    } else if (i < NW1 + NW2) {
        cvt8(W2, g_w2h, (i - NW1) * 8);
    }
}

// ---------------- CSR construction (side stream) --------------------------------
__global__ void hist_kernel(const int* __restrict__ dst) {
    int e = (blockIdx.x * blockDim.x + threadIdx.x) * 4;
    if (e >= EE) return;
    int4 d = *(const int4*)(dst + e);  // 4 independent atomics in flight
    atomicAdd(&g_cnt[d.x], 1);
    atomicAdd(&g_cnt[d.y], 1);
    atomicAdd(&g_cnt[d.z], 1);
    atomicAdd(&g_cnt[d.w], 1);
}

// Segment allocator: CSR segments need only be contiguous per node, not
// ordered — warp-scan + one atomicAdd per warp replaces a global scan.
__global__ void alloc_kernel() {
    int i = blockIdx.x * blockDim.x + threadIdx.x;
    int lane = threadIdx.x & 31;
    int v = (i < NN) ? g_cnt[i] : 0;
    int s = v;
#pragma unroll
    for (int o = 1; o < 32; o <<= 1) {
        int t = __shfl_up_sync(0xffffffffu, s, o);
        if (lane >= o) s += t;
    }
    int total = __shfl_sync(0xffffffffu, s, 31);
    int base = 0;
    if (lane == 31) base = atomicAdd(&g_total, total);
    base = __shfl_sync(0xffffffffu, base, 31);
    if (i < NN) g_off[i] = base + s - v;
}

// scatter bumps g_off directly; afterwards g_off[d] = segment END.
// Consumers recompute start = g_off[d] - g_cnt[d]. 4 edges per thread for MLP.
__global__ void scatter_kernel(const int* __restrict__ src,
                               const int* __restrict__ dst) {
    int e = (blockIdx.x * blockDim.x + threadIdx.x) * 4;
    if (e >= EE) return;
    int4 s4 = *(const int4*)(src + e);
    int4 d4 = *(const int4*)(dst + e);
    int p0 = atomicAdd(&g_off[d4.x], 1);
    int p1 = atomicAdd(&g_off[d4.y], 1);
    int p2 = atomicAdd(&g_off[d4.z], 1);
    int p3 = atomicAdd(&g_off[d4.w], 1);
    g_csr[p0] = s4.x;
    g_csr[p1] = s4.y;
    g_csr[p2] = s4.z;
    g_csr[p3] = s4.w;
}

// ---------------- cp.async helper ----------------------------------------------
__device__ __forceinline__ void cpa16(void* s, const void* g) {
    unsigned int sa = (unsigned int)__cvta_generic_to_shared(s);
    asm volatile("cp.async.cg.shared.global [%0], [%1], 16;" ::"r"(sa), "l"(g));
}

// ---------------- GEMM via tensor cores + fused attention coefficients ---------
// Ch[n,M] = half(A[n,128] @ B[128,M]); als/ald[n,M/32] fused in epilogue.
// A32=true: A is fp32, converted to fp16 in-flight (register-staged LDG one
// tile ahead -> cvt -> STS); A32=false: A is fp16, staged via cp.async.
// B always cp.async. Block tile 128x128, 8 warps (4x2), warp 32x64.
// OOB A rows are index-clamped (their outputs are discarded, never stored).
#define AS_STRIDE 40
#define BS_STRIDE 136
#define BS_OFF (2 * 128 * AS_STRIDE * 2)  // bytes, after double-buffered A
template <bool A32>
__global__ __launch_bounds__(256) void gemm_wmma(const void* __restrict__ Av,
                                                 const __half* __restrict__ B,
                                                 __half* __restrict__ C,
                                                 const float* __restrict__ a_s,
                                                 const float* __restrict__ a_d,
                                                 float* __restrict__ als,
                                                 float* __restrict__ ald,
                                                 int n, int M) {
    __shared__ __align__(16) char smem_raw[38016];
    __half (*As)[AS_STRIDE] = (__half(*)[AS_STRIDE])smem_raw;     // [2*128][40]
    __half (*Bs)[BS_STRIDE] = (__half(*)[BS_STRIDE])(smem_raw + BS_OFF); // [2*32][136]

    const float* Af = (const float*)Av;
    const __half* Ah = (const __half*)Av;

    int tid = threadIdx.x;
    int w = tid >> 5, lane = tid & 31;
    int wr = w >> 1, wc = w & 1;  // 4x2 warp grid -> warp tile 32(r) x 64(c)
    int rowBase = blockIdx.x * 128, colBase = blockIdx.y * 128;

    wmma::fragment<wmma::accumulator, 16, 16, 16, float> acc[2][4];
#pragma unroll
    for (int i = 0; i < 2; i++)
#pragma unroll
        for (int j = 0; j < 4; j++) wmma::fill_fragment(acc[i][j], 0.f);

    float4 aregs[2][2];  // A32 path: 2 chunks x 8 floats, staged one tile ahead

    auto ldgA = [&](int kt) {  // A32: issue global loads for tile kt
#pragma unroll
        for (int t = 0; t < 2; t++) {
            int c = tid + t * 256;
            int r = c >> 2, q = c & 3;
            int gr = min(rowBase + r, n - 1);  // clamp: OOB rows discarded
            const float* src = Af + (size_t)gr * 128 + kt * 32 + q * 8;
            aregs[t][0] = *(const float4*)src;
            aregs[t][1] = *(const float4*)(src + 4);
        }
    };
    auto stsA = [&](int buf) {  // A32: convert staged regs, store to smem
#pragma unroll
        for (int t = 0; t < 2; t++) {
            int c = tid + t * 256;
            int r = c >> 2, q = c & 3;
            __half2 h[4] = {
                __floats2half2_rn(aregs[t][0].x, aregs[t][0].y),
                __floats2half2_rn(aregs[t][0].z, aregs[t][0].w),
                __floats2half2_rn(aregs[t][1].x, aregs[t][1].y),
                __floats2half2_rn(aregs[t][1].z, aregs[t][1].w)};
            *(uint4*)&As[buf * 128 + r][q * 8] = *(uint4*)h;
        }
    };
    auto cpaA = [&](int kt, int buf) {  // fp16 A path
#pragma unroll
        for (int c = tid; c < 512; c += 256) {
            int r = c >> 2, q = c & 3;
            int gr = min(rowBase + r, n - 1);
            cpa16(&As[buf * 128 + r][q * 8],
                  Ah + (size_t)gr * 128 + kt * 32 + q * 8);
        }
    };
    auto cpaB = [&](int kt, int buf) {
#pragma unroll
        for (int c = tid; c < 512; c += 256) {
            int r = c >> 4, q = c & 15;
            cpa16(&Bs[buf * 32 + r][q * 8],
                  B + (size_t)(kt * 32 + r) * M + colBase + q * 8);
        }
        asm volatile("cp.async.commit_group;");
    };

    // prologue: tile 0 in flight
    if (A32) ldgA(0); else cpaA(0, 0);
    cpaB(0, 0);

    const int NT = 4;  // K = 128 / BK = 32
    for (int kt = 0; kt < NT; kt++) {
        int buf = kt & 1;
        if (A32) stsA(buf);  // consume staged regs for tile kt
        asm volatile("cp.async.wait_group 0;");
        __syncthreads();
        if (kt + 1 < NT) {  // stage tile kt+1; latency hides under MMA below
            if (A32) ldgA(kt + 1); else cpaA(kt + 1, buf ^ 1);
            cpaB(kt + 1, buf ^ 1);
        }
#pragma unroll
        for (int kk = 0; kk < 32; kk += 16) {
            wmma::fragment<wmma::matrix_a, 16, 16, 16, __half, wmma::row_major> af[2];
            wmma::fragment<wmma::matrix_b, 16, 16, 16, __half, wmma::row_major> bf[4];
#pragma unroll
            for (int i = 0; i < 2; i++)
                wmma::load_matrix_sync(
                    af[i], &As[buf * 128 + wr * 32 + i * 16][kk], AS_STRIDE);
#pragma unroll
            for (int j = 0; j < 4; j++)
                wmma::load_matrix_sync(
                    bf[j], &Bs[buf * 32 + kk][wc * 64 + j * 16], BS_STRIDE);
#pragma unroll
            for (int i = 0; i < 2; i++)
#pragma unroll
                for (int j = 0; j < 4; j++)
                    wmma::mma_sync(acc[i][j], af[i], bf[j], acc[i][j]);
        }
    }
    __syncthreads();  // smem reuse below

    // epilogue: two 32x32 passes per warp via smem staging (4608B per warp)
    float (*Cs)[36] = (float(*)[36])(smem_raw + (size_t)w * 32 * 36 * 4);
    int row = rowBase + wr * 32 + lane;
#pragma unroll
    for (int jh = 0; jh < 2; jh++) {
#pragma unroll
        for (int i = 0; i < 2; i++)
#pragma unroll
            for (int j = 0; j < 2; j++)
                wmma::store_matrix_sync(&Cs[i * 16][j * 16], acc[i][jh * 2 + j],
                                        36, wmma::mem_row_major);
        __syncwarp();
        if (row < n) {
            float vals[32];
#pragma unroll
            for (int q = 0; q < 8; q++)
                *(float4*)&vals[q * 4] = *(const float4*)&Cs[lane][q * 4];

            __half2 hh[16];
#pragma unroll
            for (int t = 0; t < 16; t++)
                hh[t] = __floats2half2_rn(vals[2 * t], vals[2 * t + 1]);
            __half* cp = C + (size_t)row * M + colBase + wc * 64 + jh * 32;
            *(uint4*)(cp + 0)  = *(uint4*)&hh[0];
            *(uint4*)(cp + 8)  = *(uint4*)&hh[4];
            *(uint4*)(cp + 16) = *(uint4*)&hh[8];
            *(uint4*)(cp + 24) = *(uint4*)&hh[12];

            int head = (colBase + wc * 64 + jh * 32) >> 5;
            const float* asv = a_s + head * 32;
            const float* adv = a_d + head * 32;
            float sv = 0.f, dv = 0.f;
#pragma unroll
            for (int c = 0; c < 32; c++) {
                sv = fmaf(vals[c], asv[c], sv);
                dv = fmaf(vals[c], adv[c], dv);
            }
            int heads = M >> 5;
            als[row * heads + head] = sv;
            ald[row * heads + head] = dv;
        }
        __syncwarp();
    }
}

// ---------------- fused GAT aggregation: one warp per destination node ---------
// exp without max subtraction (softmax is shift-invariant; max is detached in
// the reference, logits are O(±5), so this is numerically safe at 1e-3).
// Features gathered in fp16 (single vector load), accumulated in fp32.
// Full 32-edge blocks use a fixed-trip unrolled loop (4 edges' loads batched
// by the compiler -> MLP 4 on the L2 gather chain); single accumulator set
// keeps register pressure at the round-5 level. Dynamic tail for <32 edges.
// CLEANUP=true (last layer): zero g_cnt/g_total for the next replay.
template <int HEADS, int W, bool RELU, bool CLEANUP>
__global__ __launch_bounds__(256) void agg_kernel(
    const __half* __restrict__ h, const float* __restrict__ als,
    const float* __restrict__ ald, const float* __restrict__ bias,
    __half* __restrict__ zout) {
    constexpr int V = W / 32;  // channels per lane (4 or 8)
    int node = (blockIdx.x * blockDim.x + threadIdx.x) >> 5;
    int lane = threadIdx.x & 31;
    if (node >= NN) return;
    int head = (lane * V) >> 5;  // lane owns V consecutive channels of one head
    float aldh = ald[node * HEADS + head];
    float acc[V] = {};
    float den = 0.f;

    auto doEdge = [&](int s) {
        float e = als[s * HEADS + head] + aldh;
        e = e > 0.f ? e : 0.2f * e;  // LeakyReLU(0.2)
        float ex = __expf(e);
        den += ex;
        const __half* p = h + (size_t)s * W + lane * V;
        __half2 hv[V / 2];
        if (V == 8)
            *(uint4*)hv = *(const uint4*)p;
        else
            *(uint2*)hv = *(const uint2*)p;
#pragma unroll
        for (int q = 0; q < V / 2; q++) {
            float2 f = __half22float2(hv[q]);
            acc[q * 2 + 0] += ex * f.x;
            acc[q * 2 + 1] += ex * f.y;
        }
    };

    doEdge(node);  // self loop (add_self_loops=True)

    int m = g_cnt[node];
    int start = g_off[node] - m;  // g_off holds segment end post-scatter
    if (CLEANUP && lane == 0) {
        g_cnt[node] = 0;  // leave counters clean for the next run
        if (node == 0) g_total = 0;
    }
    int j0 = 0;
    for (; j0 + 32 <= m; j0 += 32) {  // full blocks: fixed trip, unrolled
        int myS = g_csr[start + j0 + lane];
#pragma unroll 4
        for (int k = 0; k < 32; k++) {
            int s = __shfl_sync(0xffffffffu, myS, k);
            doEdge(s);
        }
    }
    if (j0 < m) {  // tail (< 32 edges)
        int myS = (j0 + lane < m) ? g_csr[start + j0 + lane] : 0;
        int lim = m - j0;
        for (int k = 0; k < lim; k++) {
            int s = __shfl_sync(0xffffffffu, myS, k);
            doEdge(s);
        }
    }

    float inv = 1.f / (den + 1e-16f);
    __half2 oh[V / 2];
#pragma unroll
    for (int q = 0; q < V / 2; q++) {
        float ox = acc[q * 2 + 0] * inv + bias[lane * V + q * 2 + 0];
        float oy = acc[q * 2 + 1] * inv + bias[lane * V + q * 2 + 1];
        if (RELU) {
            ox = fmaxf(ox, 0.f);
            oy = fmaxf(oy, 0.f);
        }
        oh[q] = __floats2half2_rn(ox, oy);
    }
    if (V == 8)
        *(uint4*)(zout + (size_t)node * W + lane * V) = *(uint4*)oh;
    else
        *(uint2*)(zout + (size_t)node * W + lane * V) = *(uint2*)oh;
}

// ---------------- decode: logits = sum(z2[a] * z2[b]), 2 edges per warp --------
__global__ __launch_bounds__(256) void decode_kernel(
    const int* __restrict__ pos, const int* __restrict__ neg,
    float* __restrict__ out) {
    int warp = (blockIdx.x * blockDim.x + threadIdx.x) >> 5;
    int lane = threadIdx.x & 31;
    int half = lane >> 4, l16 = lane & 15;
    int idx = warp * 2 + half;
    if (idx >= 2 * EDEC) return;
    int a, b;
    if (idx < EDEC) {
        a = pos[idx];
        b = pos[EDEC + idx];
    } else {
        int k = idx - EDEC;
        a = neg[k];
        b = neg[EDEC + k];
    }
    const __half* pa = g_z2 + (size_t)a * F2 + l16 * 16;
    const __half* pb = g_z2 + (size_t)b * F2 + l16 * 16;
    uint4 ra0 = *(const uint4*)pa, ra1 = *(const uint4*)(pa + 8);
    uint4 rb0 = *(const uint4*)pb, rb1 = *(const uint4*)(pb + 8);
    __half2* ha0 = (__half2*)&ra0;
    __half2* ha1 = (__half2*)&ra1;
    __half2* hb0 = (__half2*)&rb0;
    __half2* hb1 = (__half2*)&rb1;
    float s = 0.f;
#pragma unroll
    for (int q = 0; q < 4; q++) {
        float2 fa = __half22float2(ha0[q]);
        float2 fb = __half22float2(hb0[q]);
        s = fmaf(fa.x, fb.x, s);
        s = fmaf(fa.y, fb.y, s);
        fa = __half22float2(ha1[q]);
        fb = __half22float2(hb1[q]);
        s = fmaf(fa.x, fb.x, s);
        s = fmaf(fa.y, fb.y, s);
    }
#pragma unroll
    for (int o = 8; o; o >>= 1) s += __shfl_xor_sync(0xffffffffu, s, o);
    if (l16 == 0) out[idx] = s;
}

// ---------------- launch --------------------------------------------------------
extern "C" void kernel_launch(void* const* d_in, const int* in_sizes, int n_in,
                              void* d_out, int out_size) {
    const float* x   = (const float*)d_in[0];
    const int*   ei  = (const int*)d_in[1];
    const int*   pos = (const int*)d_in[2];
    const int*   neg = (const int*)d_in[3];
    const float* W1  = (const float*)d_in[4];
    const float* as1 = (const float*)d_in[5];
    const float* ad1 = (const float*)d_in[6];
    const float* b1  = (const float*)d_in[7];
    const float* W2  = (const float*)d_in[8];
    const float* as2 = (const float*)d_in[9];
    const float* ad2 = (const float*)d_in[10];
    const float* b2  = (const float*)d_in[11];
    float* out = (float*)d_out;

    __half *w1hp, *w2hp, *h1p, *z1p, *h2p, *z2p;
    float *als1p, *ald1p, *als2p, *ald2p;
    cudaGetSymbolAddress((void**)&w1hp, g_w1h);
    cudaGetSymbolAddress((void**)&w2hp, g_w2h);
    cudaGetSymbolAddress((void**)&h1p, g_h1);
    cudaGetSymbolAddress((void**)&z1p, g_z1);
    cudaGetSymbolAddress((void**)&h2p, g_h2);
    cudaGetSymbolAddress((void**)&z2p, g_z2);
    cudaGetSymbolAddress((void**)&als1p, g_als1);
    cudaGetSymbolAddress((void**)&ald1p, g_ald1);
    cudaGetSymbolAddress((void**)&als2p, g_als2);
    cudaGetSymbolAddress((void**)&ald2p, g_ald2);

    // Side stream + events (created once on the first, uncaptured correctness
    // call; captured replays reuse the handles — captured WORK is identical).
    static cudaStream_t s1 = nullptr;
    static cudaEvent_t evFork = nullptr, evCsr = nullptr;
    if (s1 == nullptr) {
        cudaStreamCreateWithFlags(&s1, cudaStreamNonBlocking);
        cudaEventCreateWithFlags(&evFork, cudaEventDisableTiming);
        cudaEventCreateWithFlags(&evCsr, cudaEventDisableTiming);
    }

    const int TB = 256;
    int nodeWarpBlocks = (NN * 32 + TB - 1) / TB;  // 6250
    const int CVT_THREADS = F1 * F1 / 8 + F1 * F2 / 8;  // W1+W2 only

    // Fork: full CSR chain (hist -> alloc -> scatter) on side stream.
    // Counters are zero at entry, so hist has no dependency on main work.
    cudaEventRecord(evFork, 0);
    cudaStreamWaitEvent(s1, evFork, 0);
    hist_kernel<<<(EE / 4 + TB - 1) / TB, TB, 0, s1>>>(ei + EE);
    alloc_kernel<<<(NN + TB - 1) / TB, TB, 0, s1>>>();
    scatter_kernel<<<(EE / 4 + TB - 1) / TB, TB, 0, s1>>>(ei, ei + EE);
    cudaEventRecord(evCsr, s1);

    // Main: weight converts (tiny), then layer-1 GEMM consuming fp32 x directly
    // (x conversion folded into the GEMM A-stage). Overlapped with CSR build.
    cvt_kernel<<<(CVT_THREADS + TB - 1) / TB, TB>>>(W1, W2);
    gemm_wmma<true><<<dim3((NN + 127) / 128, F1 / 128), TB>>>(
        x, w1hp, h1p, as1, ad1, als1p, ald1p, NN, F1);

    // Join: agg1 needs both gemm1 (main) and the CSR build (s1).
    cudaStreamWaitEvent(0, evCsr, 0);
    agg_kernel<4, F1, true, false><<<nodeWarpBlocks, TB>>>(
        h1p, als1p, ald1p, b1, z1p);

    // Layer 2 (cleans counters for next run)
    gemm_wmma<false><<<dim3((NN + 127) / 128, F2 / 128), TB>>>(
        z1p, w2hp, h2p, as2, ad2, als2p, ald2p, NN, F2);
    agg_kernel<8, F2, false, true><<<nodeWarpBlocks, TB>>>(
        h2p, als2p, ald2p, b2, z2p);

    // Decode
    decode_kernel<<<(EDEC * 32 + TB - 1) / TB, TB>>>(pos, neg, out);
}